// round 8
// baseline (speedup 1.0000x reference)
#include <cuda_runtime.h>
#include <cuda_bf16.h>

// Fixed shapes: B=4, L=2048
#define BQ 4
#define LQ 2048
#define MSEG (LQ - 1)              // 2047 segments per path

#define THREADS 256
#define UI 2                        // i-segments per thread
#define IPB (THREADS * UI)          // 512
#define IT 4                        // ceil(2047/512)
#define JT 37
#define JPB 56                      // ceil(2047/37)
#define NBLOCKS (BQ * IT * JT)      // 592 = 148 SMs * 4 CTAs
#define PER_B (IT * JT)             // 148 partials per batch

// Scratch (no cudaMalloc allowed)
__device__ float        g_partial[NBLOCKS];
__device__ unsigned int g_count = 0;

__device__ __forceinline__ float3 norm_imag4(float4 q) {
    float s  = q.x * q.x + q.y * q.y + q.z * q.z + q.w * q.w;
    float rs = rsqrtf(fmaxf(s, 1e-30f));
    float nrm = s * rs;                          // |q|
    float inv = __fdividef(1.0f, nrm + 1e-12f);
    return make_float3(q.y * inv, q.z * inv, q.w * inv);
}

__global__ __launch_bounds__(THREADS, 4)
void gauss_linking_fused(const float* __restrict__ qa,
                         const float* __restrict__ qb,
                         float* __restrict__ out) {
    __shared__ float  pA[(IPB + 1) * 3];                 // 6.2 KB
    __shared__ float  pB[(JPB + 1) * 3];
    __shared__ __align__(16) float sj[JPB * 12];         // rb(3) db(3) g(3) pad(3)
    __shared__ float  red[THREADS];
    __shared__ double sdd[BQ];
    __shared__ int    lastFlag;

    const int b  = blockIdx.z;
    const int it = blockIdx.y;
    const int jt = blockIdx.x;
    const int t  = threadIdx.x;

    // ---- Stage & normalize A-point tile ----
    const int i0     = it * IPB;
    const int segcnt = min(IPB, MSEG - i0);              // 512 or 511
    for (int p = t; p < segcnt + 1; p += THREADS) {
        float4 q = *reinterpret_cast<const float4*>(qa + ((long)(b * LQ + i0 + p)) * 4);
        float3 v = norm_imag4(q);
        pA[p * 3 + 0] = v.x; pA[p * 3 + 1] = v.y; pA[p * 3 + 2] = v.z;
    }

    // ---- Stage & normalize B-point tile, build per-j data (rb, db, g=rb x db) ----
    const int j0     = jt * JPB;
    const int jcount = min(JPB, MSEG - j0);              // 56 (31 for last tile)
    if (t <= jcount) {
        float4 q = *reinterpret_cast<const float4*>(qb + ((long)(b * LQ + j0 + t)) * 4);
        float3 v = norm_imag4(q);
        pB[t * 3 + 0] = v.x; pB[t * 3 + 1] = v.y; pB[t * 3 + 2] = v.z;
    }
    __syncthreads();
    if (t < jcount) {
        float x0 = pB[t * 3 + 0], y0 = pB[t * 3 + 1], z0 = pB[t * 3 + 2];
        float x1 = pB[t * 3 + 3], y1 = pB[t * 3 + 4], z1 = pB[t * 3 + 5];
        float rbx = (x1 + x0) * 0.5f, rby = (y1 + y0) * 0.5f, rbz = (z1 + z0) * 0.5f;
        float dbx = x1 - x0,          dby = y1 - y0,          dbz = z1 - z0;
        float gx = rby * dbz - rbz * dby;                 // g = rb x db
        float gy = rbz * dbx - rbx * dbz;
        float gz = rbx * dby - rby * dbx;
        float* s = sj + t * 12;
        s[0] = rbx; s[1] = rby; s[2] = rbz;
        s[3] = dbx; s[4] = dby; s[5] = dbz;
        s[6] = gx;  s[7] = gy;  s[8] = gz;
    }
    __syncthreads();

    // ---- Register-resident i-segments: ra, da, ha = ra x da ----
    float ax[UI], ay[UI], az[UI], dax[UI], day[UI], daz[UI];
    float hax[UI], hay[UI], haz[UI];
    #pragma unroll
    for (int u = 0; u < UI; u++) {
        int i = u * THREADS + t;
        if (i < segcnt) {
            float x0 = pA[i * 3 + 0], y0 = pA[i * 3 + 1], z0 = pA[i * 3 + 2];
            float x1 = pA[i * 3 + 3], y1 = pA[i * 3 + 4], z1 = pA[i * 3 + 5];
            ax[u]  = (x1 + x0) * 0.5f; ay[u]  = (y1 + y0) * 0.5f; az[u]  = (z1 + z0) * 0.5f;
            dax[u] = x1 - x0;          day[u] = y1 - y0;          daz[u] = z1 - z0;
            hax[u] = ay[u] * daz[u] - az[u] * day[u];     // ha = ra x da
            hay[u] = az[u] * dax[u] - ax[u] * daz[u];
            haz[u] = ax[u] * day[u] - ay[u] * dax[u];
        } else {
            ax[u] = ay[u] = az[u] = 0.f;
            dax[u] = day[u] = daz[u] = 0.f;
            hax[u] = hay[u] = haz[u] = 0.f;               // num = 0 -> contributes 0
        }
    }

    // ---- Main all-pairs loop ----
    // num = rd.(da x db) = (ra x da).db + da.(rb x db) = ha.db + da.g
    // 1/(|r|+eps)^3 ~= 1/(d2*|r| + 3eps*d2)   (eps = 1e-6; O(eps^2) dropped)
    float acc = 0.0f;
    #pragma unroll 2
    for (int j = 0; j < jcount; j++) {
        const float4 v0 = *reinterpret_cast<const float4*>(sj + j * 12);      // rbx rby rbz dbx
        const float4 v1 = *reinterpret_cast<const float4*>(sj + j * 12 + 4);  // dby dbz gx gy
        const float  gz = sj[j * 12 + 8];
        #pragma unroll
        for (int u = 0; u < UI; u++) {
            float rdx = ax[u] - v0.x;
            float rdy = ay[u] - v0.y;
            float rdz = az[u] - v0.z;
            float d2  = fmaf(rdx, rdx, fmaf(rdy, rdy, rdz * rdz));
            d2 = fmaxf(d2, 1e-24f);
            float num = fmaf(hax[u], v0.w, fmaf(hay[u], v1.x, haz[u] * v1.y));
            num = fmaf(dax[u], v1.z, fmaf(day[u], v1.w, fmaf(daz[u], gz, num)));
            float rs   = rsqrtf(d2);
            float den3 = d2 * fmaf(d2, rs, 3e-6f);
            float inv3;
            asm("rcp.approx.f32 %0, %1;" : "=f"(inv3) : "f"(den3));
            acc = fmaf(num, inv3, acc);
        }
    }

    // ---- Deterministic block tree-reduce ----
    red[t] = acc;
    __syncthreads();
    #pragma unroll
    for (int off = THREADS / 2; off >= 1; off >>= 1) {
        if (t < off) red[t] += red[t + off];
        __syncthreads();
    }

    // ---- Last-block-done final reduction (deterministic fixed order) ----
    if (t == 0) {
        g_partial[b * PER_B + it * JT + jt] = red[0];
        __threadfence();
        unsigned int tk = atomicAdd(&g_count, 1u);
        lastFlag = (tk == NBLOCKS - 1u) ? 1 : 0;
    }
    __syncthreads();

    if (lastFlag) {
        int w = t >> 5, l = t & 31;
        if (w < BQ) {
            double s = 0.0;
            for (int k = l; k < PER_B; k += 32)
                s += (double)__ldcg(&g_partial[w * PER_B + k]);
            #pragma unroll
            for (int off = 16; off >= 1; off >>= 1)
                s += __shfl_down_sync(0xffffffffu, s, off);
            if (l == 0) sdd[w] = fabs(s);
        }
        __syncthreads();
        if (t == 0) {
            double tot = sdd[0] + sdd[1] + sdd[2] + sdd[3];
            out[0] = (float)(tot / ((double)BQ * 4.0 * 3.14159265358979323846));
            g_count = 0;   // reset for next graph replay
        }
    }
}

extern "C" void kernel_launch(void* const* d_in, const int* in_sizes, int n_in,
                              void* d_out, int out_size) {
    const float* qa = (const float*)d_in[0];   // genomic_quats [B,L,4]
    const float* qb = (const float*)d_in[1];   // code_quats    [B,L,4]
    float* out = (float*)d_out;

    dim3 grid(JT, IT, BQ);                     // 592 blocks
    gauss_linking_fused<<<grid, THREADS>>>(qa, qb, out);
}

// round 9
// speedup vs baseline: 1.1774x; 1.1774x over previous
#include <cuda_runtime.h>
#include <cuda_bf16.h>

// Fixed shapes: B=4, L=2048
#define BQ 4
#define LQ 2048
#define MSEG (LQ - 1)              // 2047 segments per path

#define THREADS 256
#define UI 2                        // i-segments per thread (packed into f32x2)
#define IPB (THREADS * UI)          // 512
#define IT 4                        // ceil(2047/512)
#define JT 37
#define JPB 56                      // ceil(2047/37)
#define NBLOCKS (BQ * IT * JT)      // 592 = 148 SMs * 4 CTAs
#define PER_B (IT * JT)             // 148 partials per batch

typedef unsigned long long u64;

// Scratch (no cudaMalloc allowed)
__device__ float        g_partial[NBLOCKS];
__device__ unsigned int g_count = 0;

// ---- packed f32x2 helpers (sm_100+ PTX) ----
__device__ __forceinline__ u64 pk2(float lo, float hi) {
    u64 r; asm("mov.b64 %0, {%1, %2};" : "=l"(r) : "f"(lo), "f"(hi)); return r;
}
__device__ __forceinline__ void upk2(u64 v, float& lo, float& hi) {
    asm("mov.b64 {%0, %1}, %2;" : "=f"(lo), "=f"(hi) : "l"(v));
}
__device__ __forceinline__ u64 f2fma(u64 a, u64 b, u64 c) {
    u64 d; asm("fma.rn.f32x2 %0, %1, %2, %3;" : "=l"(d) : "l"(a), "l"(b), "l"(c)); return d;
}
__device__ __forceinline__ u64 f2add(u64 a, u64 b) {
    u64 d; asm("add.rn.f32x2 %0, %1, %2;" : "=l"(d) : "l"(a), "l"(b)); return d;
}
__device__ __forceinline__ u64 f2mul(u64 a, u64 b) {
    u64 d; asm("mul.rn.f32x2 %0, %1, %2;" : "=l"(d) : "l"(a), "l"(b)); return d;
}

__device__ __forceinline__ float3 norm_imag4(float4 q) {
    float s  = q.x * q.x + q.y * q.y + q.z * q.z + q.w * q.w;
    float rs = rsqrtf(fmaxf(s, 1e-30f));
    float nrm = s * rs;                          // |q|
    float inv = __fdividef(1.0f, nrm + 1e-12f);
    return make_float3(q.y * inv, q.z * inv, q.w * inv);
}

__global__ __launch_bounds__(THREADS, 4)
void gauss_linking_fused(const float* __restrict__ qa,
                         const float* __restrict__ qb,
                         float* __restrict__ out) {
    __shared__ float  pA[(IPB + 1) * 3];                 // 6.2 KB
    __shared__ float  pB[(JPB + 1) * 3];
    // per-j packed duplicated operands: {-rbx,-rby,-rbz, dbx,dby,dbz, gx,gy,gz} + pad
    __shared__ __align__(16) u64 sj[JPB * 10];           // 4.4 KB
    __shared__ float  red[THREADS];
    __shared__ double sdd[BQ];
    __shared__ int    lastFlag;

    const int b  = blockIdx.z;
    const int it = blockIdx.y;
    const int jt = blockIdx.x;
    const int t  = threadIdx.x;

    // ---- Stage & normalize A-point tile ----
    const int i0     = it * IPB;
    const int segcnt = min(IPB, MSEG - i0);              // 512 or 511
    for (int p = t; p < segcnt + 1; p += THREADS) {
        float4 q = *reinterpret_cast<const float4*>(qa + ((long)(b * LQ + i0 + p)) * 4);
        float3 v = norm_imag4(q);
        pA[p * 3 + 0] = v.x; pA[p * 3 + 1] = v.y; pA[p * 3 + 2] = v.z;
    }

    // ---- Stage & normalize B-point tile, build duplicated per-j data ----
    const int j0     = jt * JPB;
    const int jcount = min(JPB, MSEG - j0);              // 56 (31 for last tile)
    if (t <= jcount) {
        float4 q = *reinterpret_cast<const float4*>(qb + ((long)(b * LQ + j0 + t)) * 4);
        float3 v = norm_imag4(q);
        pB[t * 3 + 0] = v.x; pB[t * 3 + 1] = v.y; pB[t * 3 + 2] = v.z;
    }
    __syncthreads();
    if (t < jcount) {
        float x0 = pB[t * 3 + 0], y0 = pB[t * 3 + 1], z0 = pB[t * 3 + 2];
        float x1 = pB[t * 3 + 3], y1 = pB[t * 3 + 4], z1 = pB[t * 3 + 5];
        float rbx = (x1 + x0) * 0.5f, rby = (y1 + y0) * 0.5f, rbz = (z1 + z0) * 0.5f;
        float dbx = x1 - x0,          dby = y1 - y0,          dbz = z1 - z0;
        float gx = rby * dbz - rbz * dby;                 // g = rb x db
        float gy = rbz * dbx - rbx * dbz;
        float gz = rbx * dby - rby * dbx;
        u64* s = sj + t * 10;
        s[0] = pk2(-rbx, -rbx);  s[1] = pk2(-rby, -rby);  s[2] = pk2(-rbz, -rbz);
        s[3] = pk2(dbx, dbx);    s[4] = pk2(dby, dby);    s[5] = pk2(dbz, dbz);
        s[6] = pk2(gx, gx);      s[7] = pk2(gy, gy);      s[8] = pk2(gz, gz);
    }
    __syncthreads();

    // ---- Register-resident i-segments, packed (u=0 in lo, u=1 in hi) ----
    float ax[UI], ay[UI], az[UI], dax[UI], day[UI], daz[UI];
    float hax[UI], hay[UI], haz[UI];
    #pragma unroll
    for (int u = 0; u < UI; u++) {
        int i = u * THREADS + t;
        if (i < segcnt) {
            float x0 = pA[i * 3 + 0], y0 = pA[i * 3 + 1], z0 = pA[i * 3 + 2];
            float x1 = pA[i * 3 + 3], y1 = pA[i * 3 + 4], z1 = pA[i * 3 + 5];
            ax[u]  = (x1 + x0) * 0.5f; ay[u]  = (y1 + y0) * 0.5f; az[u]  = (z1 + z0) * 0.5f;
            dax[u] = x1 - x0;          day[u] = y1 - y0;          daz[u] = z1 - z0;
            hax[u] = ay[u] * daz[u] - az[u] * day[u];     // ha = ra x da
            hay[u] = az[u] * dax[u] - ax[u] * daz[u];
            haz[u] = ax[u] * day[u] - ay[u] * dax[u];
        } else {
            ax[u] = ay[u] = az[u] = 0.f;
            dax[u] = day[u] = daz[u] = 0.f;
            hax[u] = hay[u] = haz[u] = 0.f;               // num = 0 -> contributes 0
        }
    }
    const u64 axp  = pk2(ax[0],  ax[1]),  ayp  = pk2(ay[0],  ay[1]),  azp  = pk2(az[0],  az[1]);
    const u64 daxp = pk2(dax[0], dax[1]), dayp = pk2(day[0], day[1]), dazp = pk2(daz[0], daz[1]);
    const u64 haxp = pk2(hax[0], hax[1]), hayp = pk2(hay[0], hay[1]), hazp = pk2(haz[0], haz[1]);
    const u64 NEG3EPS = pk2(-3e-6f, -3e-6f);
    const u64 ONE2    = pk2(1.0f, 1.0f);

    // ---- Main all-pairs loop (fully packed f32x2) ----
    // num = rd.(da x db) = (ra x da).db + da.(rb x db) = ha.db + da.g
    // 1/(|r|+eps)^3 = rs^3 * (1+eps*rs)^-3 ~= rs^3 * (1 - 3*eps*rs)
    u64 acc2 = 0ull;
    #pragma unroll 4
    for (int j = 0; j < jcount; j++) {
        const u64* s = sj + j * 10;
        ulonglong2 p01 = *reinterpret_cast<const ulonglong2*>(s);      // -rbx -rby
        ulonglong2 p23 = *reinterpret_cast<const ulonglong2*>(s + 2);  // -rbz  dbx
        ulonglong2 p45 = *reinterpret_cast<const ulonglong2*>(s + 4);  //  dby  dbz
        ulonglong2 p67 = *reinterpret_cast<const ulonglong2*>(s + 6);  //  gx   gy
        u64 gz2 = s[8];

        u64 rdx = f2add(axp, p01.x);
        u64 rdy = f2add(ayp, p01.y);
        u64 rdz = f2add(azp, p23.x);
        u64 d2  = f2fma(rdz, rdz, f2fma(rdy, rdy, f2mul(rdx, rdx)));

        u64 num = f2fma(hazp, p45.y, f2fma(hayp, p45.x, f2mul(haxp, p23.y)));
        num     = f2fma(dazp, gz2,  f2fma(dayp, p67.y, f2fma(daxp, p67.x, num)));

        float d0, d1;
        upk2(d2, d0, d1);
        float r0 = rsqrtf(fmaxf(d0, 1e-24f));
        float r1 = rsqrtf(fmaxf(d1, 1e-24f));
        u64 rs  = pk2(r0, r1);
        u64 rs3 = f2mul(f2mul(rs, rs), rs);
        u64 fac = f2fma(rs, NEG3EPS, ONE2);
        acc2 = f2fma(f2mul(num, rs3), fac, acc2);
    }

    float aLo, aHi;
    upk2(acc2, aLo, aHi);
    float acc = aLo + aHi;

    // ---- Deterministic block tree-reduce ----
    red[t] = acc;
    __syncthreads();
    #pragma unroll
    for (int off = THREADS / 2; off >= 1; off >>= 1) {
        if (t < off) red[t] += red[t + off];
        __syncthreads();
    }

    // ---- Last-block-done final reduction (deterministic fixed order) ----
    if (t == 0) {
        g_partial[b * PER_B + it * JT + jt] = red[0];
        __threadfence();
        unsigned int tk = atomicAdd(&g_count, 1u);
        lastFlag = (tk == NBLOCKS - 1u) ? 1 : 0;
    }
    __syncthreads();

    if (lastFlag) {
        int w = t >> 5, l = t & 31;
        if (w < BQ) {
            double s = 0.0;
            for (int k = l; k < PER_B; k += 32)
                s += (double)__ldcg(&g_partial[w * PER_B + k]);
            #pragma unroll
            for (int off = 16; off >= 1; off >>= 1)
                s += __shfl_down_sync(0xffffffffu, s, off);
            if (l == 0) sdd[w] = fabs(s);
        }
        __syncthreads();
        if (t == 0) {
            double tot = sdd[0] + sdd[1] + sdd[2] + sdd[3];
            out[0] = (float)(tot / ((double)BQ * 4.0 * 3.14159265358979323846));
            g_count = 0;   // reset for next graph replay
        }
    }
}

extern "C" void kernel_launch(void* const* d_in, const int* in_sizes, int n_in,
                              void* d_out, int out_size) {
    const float* qa = (const float*)d_in[0];   // genomic_quats [B,L,4]
    const float* qb = (const float*)d_in[1];   // code_quats    [B,L,4]
    float* out = (float*)d_out;

    dim3 grid(JT, IT, BQ);                     // 592 blocks
    gauss_linking_fused<<<grid, THREADS>>>(qa, qb, out);
}

// round 11
// speedup vs baseline: 1.3069x; 1.1099x over previous
#include <cuda_runtime.h>
#include <cuda_bf16.h>

// Fixed shapes: B=4, L=2048
#define BQ 4
#define LQ 2048
#define MSEG (LQ - 1)              // 2047 segments per path

#define THREADS 256
#define NSET 2                      // packed f32x2 sets per thread
#define UI (2 * NSET)               // 4 i-segments per thread
#define IPB (THREADS * UI)          // 1024
#define IT 2                        // ceil(2047/1024)
#define JT 54
#define JPB 38                      // 54*38 = 2052 >= 2047
#define NBLOCKS (BQ * IT * JT)      // 432 <= 148 SMs * 3 CTAs
#define PER_B (IT * JT)             // 108 partials per batch

typedef unsigned long long u64;

// Scratch (no cudaMalloc allowed)
__device__ float        g_partial[NBLOCKS];
__device__ unsigned int g_count = 0;

// ---- packed f32x2 helpers (sm_100+ PTX) ----
__device__ __forceinline__ u64 pk2(float lo, float hi) {
    u64 r; asm("mov.b64 %0, {%1, %2};" : "=l"(r) : "f"(lo), "f"(hi)); return r;
}
__device__ __forceinline__ void upk2(u64 v, float& lo, float& hi) {
    asm("mov.b64 {%0, %1}, %2;" : "=f"(lo), "=f"(hi) : "l"(v));
}
__device__ __forceinline__ u64 f2fma(u64 a, u64 b, u64 c) {
    u64 d; asm("fma.rn.f32x2 %0, %1, %2, %3;" : "=l"(d) : "l"(a), "l"(b), "l"(c)); return d;
}
__device__ __forceinline__ u64 f2add(u64 a, u64 b) {
    u64 d; asm("add.rn.f32x2 %0, %1, %2;" : "=l"(d) : "l"(a), "l"(b)); return d;
}
__device__ __forceinline__ u64 f2mul(u64 a, u64 b) {
    u64 d; asm("mul.rn.f32x2 %0, %1, %2;" : "=l"(d) : "l"(a), "l"(b)); return d;
}
__device__ __forceinline__ float frsq(float x) {
    float r; asm("rsqrt.approx.f32 %0, %1;" : "=f"(r) : "f"(x)); return r;
}

__device__ __forceinline__ float3 norm_imag4(float4 q) {
    float s  = q.x * q.x + q.y * q.y + q.z * q.z + q.w * q.w;
    float rs = rsqrtf(fmaxf(s, 1e-30f));
    float nrm = s * rs;                          // |q|
    float inv = __fdividef(1.0f, nrm + 1e-12f);
    return make_float3(q.y * inv, q.z * inv, q.w * inv);
}

__global__ __launch_bounds__(THREADS, 3)
void gauss_linking_fused(const float* __restrict__ qa,
                         const float* __restrict__ qb,
                         float* __restrict__ out) {
    __shared__ float  pA[(IPB + 1) * 3];                 // 12.3 KB
    __shared__ float  pB[(JPB + 1) * 3];
    // per-j packed duplicated operands: {-rbx,-rby,-rbz, dbx,dby,dbz, gx,gy,gz} + pad
    __shared__ __align__(16) u64 sj[JPB * 10];           // 3.0 KB
    __shared__ float  red[THREADS];
    __shared__ double sdd[BQ];
    __shared__ int    lastFlag;

    const int b  = blockIdx.z;
    const int it = blockIdx.y;
    const int jt = blockIdx.x;
    const int t  = threadIdx.x;

    // ---- Stage & normalize A-point tile ----
    const int i0     = it * IPB;
    const int segcnt = min(IPB, MSEG - i0);              // 1024 or 1023
    for (int p = t; p < segcnt + 1; p += THREADS) {
        float4 q = *reinterpret_cast<const float4*>(qa + ((long)(b * LQ + i0 + p)) * 4);
        float3 v = norm_imag4(q);
        pA[p * 3 + 0] = v.x; pA[p * 3 + 1] = v.y; pA[p * 3 + 2] = v.z;
    }

    // ---- Stage & normalize B-point tile, build duplicated per-j data ----
    const int j0     = jt * JPB;
    const int jcount = min(JPB, MSEG - j0);              // 38 (33 for last tile)
    if (t <= jcount) {
        float4 q = *reinterpret_cast<const float4*>(qb + ((long)(b * LQ + j0 + t)) * 4);
        float3 v = norm_imag4(q);
        pB[t * 3 + 0] = v.x; pB[t * 3 + 1] = v.y; pB[t * 3 + 2] = v.z;
    }
    __syncthreads();
    if (t < jcount) {
        float x0 = pB[t * 3 + 0], y0 = pB[t * 3 + 1], z0 = pB[t * 3 + 2];
        float x1 = pB[t * 3 + 3], y1 = pB[t * 3 + 4], z1 = pB[t * 3 + 5];
        float rbx = (x1 + x0) * 0.5f, rby = (y1 + y0) * 0.5f, rbz = (z1 + z0) * 0.5f;
        float dbx = x1 - x0,          dby = y1 - y0,          dbz = z1 - z0;
        float gx = rby * dbz - rbz * dby;                 // g = rb x db
        float gy = rbz * dbx - rbx * dbz;
        float gz = rbx * dby - rby * dbx;
        u64* s = sj + t * 10;
        s[0] = pk2(-rbx, -rbx);  s[1] = pk2(-rby, -rby);  s[2] = pk2(-rbz, -rbz);
        s[3] = pk2(dbx, dbx);    s[4] = pk2(dby, dby);    s[5] = pk2(dbz, dbz);
        s[6] = pk2(gx, gx);      s[7] = pk2(gy, gy);      s[8] = pk2(gz, gz);
    }
    __syncthreads();

    // ---- Register-resident i-segments, packed: set s holds (u=2s lo, u=2s+1 hi) ----
    float ax[UI], ay[UI], az[UI], dax[UI], day[UI], daz[UI];
    float hax[UI], hay[UI], haz[UI];
    #pragma unroll
    for (int u = 0; u < UI; u++) {
        int i = u * THREADS + t;
        if (i < segcnt) {
            float x0 = pA[i * 3 + 0], y0 = pA[i * 3 + 1], z0 = pA[i * 3 + 2];
            float x1 = pA[i * 3 + 3], y1 = pA[i * 3 + 4], z1 = pA[i * 3 + 5];
            ax[u]  = (x1 + x0) * 0.5f; ay[u]  = (y1 + y0) * 0.5f; az[u]  = (z1 + z0) * 0.5f;
            dax[u] = x1 - x0;          day[u] = y1 - y0;          daz[u] = z1 - z0;
            hax[u] = ay[u] * daz[u] - az[u] * day[u];     // ha = ra x da
            hay[u] = az[u] * dax[u] - ax[u] * daz[u];
            haz[u] = ax[u] * day[u] - ay[u] * dax[u];
        } else {
            ax[u] = ay[u] = az[u] = 0.f;
            dax[u] = day[u] = daz[u] = 0.f;
            hax[u] = hay[u] = haz[u] = 0.f;               // num = 0 -> contributes 0
        }
    }
    u64 axp[NSET], ayp[NSET], azp[NSET];
    u64 daxp[NSET], dayp[NSET], dazp[NSET];
    u64 haxp[NSET], hayp[NSET], hazp[NSET];
    #pragma unroll
    for (int s = 0; s < NSET; s++) {
        axp[s]  = pk2(ax[2*s],  ax[2*s+1]);  ayp[s]  = pk2(ay[2*s],  ay[2*s+1]);  azp[s]  = pk2(az[2*s],  az[2*s+1]);
        daxp[s] = pk2(dax[2*s], dax[2*s+1]); dayp[s] = pk2(day[2*s], day[2*s+1]); dazp[s] = pk2(daz[2*s], daz[2*s+1]);
        haxp[s] = pk2(hax[2*s], hax[2*s+1]); hayp[s] = pk2(hay[2*s], hay[2*s+1]); hazp[s] = pk2(haz[2*s], haz[2*s+1]);
    }
    const u64 NEG3EPS = pk2(-3e-6f, -3e-6f);
    const u64 ONE2    = pk2(1.0f, 1.0f);
    const u64 TINY2   = pk2(1e-24f, 1e-24f);

    // ---- Main all-pairs loop (fully packed f32x2, 2 independent chains) ----
    // num = rd.(da x db) = (ra x da).db + da.(rb x db) = ha.db + da.g
    // 1/(|r|+eps)^3 = rs^3 * (1+eps*rs)^-3 ~= rs^3 * (1 - 3*eps*rs)
    u64 acc2[NSET] = {0ull, 0ull};
    #pragma unroll 2
    for (int j = 0; j < jcount; j++) {
        const u64* sp = sj + j * 10;
        ulonglong2 p01 = *reinterpret_cast<const ulonglong2*>(sp);      // -rbx -rby
        ulonglong2 p23 = *reinterpret_cast<const ulonglong2*>(sp + 2);  // -rbz  dbx
        ulonglong2 p45 = *reinterpret_cast<const ulonglong2*>(sp + 4);  //  dby  dbz
        ulonglong2 p67 = *reinterpret_cast<const ulonglong2*>(sp + 6);  //  gx   gy
        u64 gz2 = sp[8];
        #pragma unroll
        for (int s = 0; s < NSET; s++) {
            u64 rdx = f2add(axp[s], p01.x);
            u64 rdy = f2add(ayp[s], p01.y);
            u64 rdz = f2add(azp[s], p23.x);
            u64 d2  = f2fma(rdx, rdx, TINY2);       // seed keeps d2 > 0 (no fmax)
            d2      = f2fma(rdy, rdy, d2);
            d2      = f2fma(rdz, rdz, d2);

            u64 num = f2fma(hazp[s], p45.y, f2fma(hayp[s], p45.x, f2mul(haxp[s], p23.y)));
            num     = f2fma(dazp[s], gz2,  f2fma(dayp[s], p67.y, f2fma(daxp[s], p67.x, num)));

            float d0, d1;
            upk2(d2, d0, d1);
            u64 rs  = pk2(frsq(d0), frsq(d1));
            u64 rs3 = f2mul(f2mul(rs, rs), rs);
            u64 fac = f2fma(rs, NEG3EPS, ONE2);
            acc2[s] = f2fma(f2mul(num, rs3), fac, acc2[s]);
        }
    }

    float l0, h0, l1, h1;
    upk2(acc2[0], l0, h0);
    upk2(acc2[1], l1, h1);
    float acc = (l0 + h0) + (l1 + h1);

    // ---- Deterministic block tree-reduce ----
    red[t] = acc;
    __syncthreads();
    #pragma unroll
    for (int off = THREADS / 2; off >= 1; off >>= 1) {
        if (t < off) red[t] += red[t + off];
        __syncthreads();
    }

    // ---- Last-block-done final reduction (deterministic fixed order) ----
    if (t == 0) {
        g_partial[b * PER_B + it * JT + jt] = red[0];
        __threadfence();
        unsigned int tk = atomicAdd(&g_count, 1u);
        lastFlag = (tk == NBLOCKS - 1u) ? 1 : 0;
    }
    __syncthreads();

    if (lastFlag) {
        int w = t >> 5, l = t & 31;
        if (w < BQ) {
            double s = 0.0;
            for (int k = l; k < PER_B; k += 32)
                s += (double)__ldcg(&g_partial[w * PER_B + k]);
            #pragma unroll
            for (int off = 16; off >= 1; off >>= 1)
                s += __shfl_down_sync(0xffffffffu, s, off);
            if (l == 0) sdd[w] = fabs(s);
        }
        __syncthreads();
        if (t == 0) {
            double tot = sdd[0] + sdd[1] + sdd[2] + sdd[3];
            out[0] = (float)(tot / ((double)BQ * 4.0 * 3.14159265358979323846));
            g_count = 0;   // reset for next graph replay
        }
    }
}

extern "C" void kernel_launch(void* const* d_in, const int* in_sizes, int n_in,
                              void* d_out, int out_size) {
    const float* qa = (const float*)d_in[0];   // genomic_quats [B,L,4]
    const float* qb = (const float*)d_in[1];   // code_quats    [B,L,4]
    float* out = (float*)d_out;

    dim3 grid(JT, IT, BQ);                     // 432 blocks
    gauss_linking_fused<<<grid, THREADS>>>(qa, qb, out);
}